// round 5
// baseline (speedup 1.0000x reference)
#include <cuda_runtime.h>
#include <cuda_bf16.h>
#include <math.h>
#include <stdint.h>

using bf16  = __nv_bfloat16;
using bf162 = __nv_bfloat162;

#define BBATCH 4
#define SSEQ   2048
#define DMOD   512
#define NHEAD  8
#define DKH    64
#define HBC    (NHEAD*BBATCH)          // 32
#define NX     (8192*512)
#define NA     ((size_t)HBC*SSEQ*DKH)
#define PAD    40                      // bf16 smem row stride

// small-tile GEMM stage: A(128xPAD h+l) + B(64xPAD h+l)
#define ATILE   (128*PAD)              // 5120
#define BTILE   (64*PAD)               // 2560
#define STG_S   (2*ATILE + 2*BTILE)    // 15360 bf16
#define SMEM_S  (2*STG_S*2)            // 61440 bytes

// pv stage: P(128xPAD h+l) + V(64xPAD h+l)
#define STG_PV  (2*ATILE + 2*BTILE)    // 15360
#define SMEM_PV (2*STG_PV*2 + 512)     // 61952 bytes

// ------------------------------ scratch -------------------------------------
__device__ bf16  g_qxh[NX], g_qxl[NX], g_kxh[NX], g_kxl[NX], g_vxh[NX], g_vxl[NX];
__device__ bf16  g_wh[4][512*512], g_wl[4][512*512];
__device__ bf16  g_Qh[NA], g_Ql[NA], g_Kh[NA], g_Kl[NA];
__device__ float g_vf[NA];
__device__ bf16  g_Vth[NA], g_Vtl[NA];
__device__ float g_l[HBC*SSEQ];
__device__ bf16  g_ch[NX], g_cl[NX];
__device__ float g_x[NX];

// ------------------------------ helpers -------------------------------------
__device__ __forceinline__ uint32_t smem_u32(const void* p) {
    return (uint32_t)__cvta_generic_to_shared(p);
}
__device__ __forceinline__ void cp16(void* s, const void* g) {
    asm volatile("cp.async.ca.shared.global [%0], [%1], 16;"
                 :: "r"(smem_u32(s)), "l"(g));
}
__device__ __forceinline__ void cp_commit() {
    asm volatile("cp.async.commit_group;" ::: "memory");
}
__device__ __forceinline__ void cp_wait0() {
    asm volatile("cp.async.wait_group 0;" ::: "memory");
}
__device__ __forceinline__ void ldm4(uint32_t a, uint32_t r[4]) {
    asm volatile("ldmatrix.sync.aligned.m8n8.x4.shared.b16 {%0,%1,%2,%3},[%4];"
                 : "=r"(r[0]), "=r"(r[1]), "=r"(r[2]), "=r"(r[3]) : "r"(a));
}
__device__ __forceinline__ void mma_bf16(float c[4], const uint32_t a[4],
                                         uint32_t b0, uint32_t b1) {
    asm volatile(
        "mma.sync.aligned.m16n8k16.row.col.f32.bf16.bf16.f32 "
        "{%0,%1,%2,%3},{%4,%5,%6,%7},{%8,%9},{%0,%1,%2,%3};"
        : "+f"(c[0]), "+f"(c[1]), "+f"(c[2]), "+f"(c[3])
        : "r"(a[0]), "r"(a[1]), "r"(a[2]), "r"(a[3]), "r"(b0), "r"(b1));
}

// Register-lean 3-term split mma over one 128x32 A / 64x32 B chunk.
// Warp tile 64x16. c is c[8][4] = c[mt*2+nt].
__device__ __forceinline__ void mma3_v2(
    const bf16* sAh, const bf16* sAl, const bf16* sBh, const bf16* sBl,
    int lane, int wm, int wn, float (*c)[4])
{
    const int lr = lane & 15;
    const int lc = (lane >> 4) * 8;
#pragma unroll
    for (int ks = 0; ks < 2; ++ks) {
        uint32_t bh[4], bl[4];
        ldm4(smem_u32(sBh + (wn + lr)*PAD + ks*16 + lc), bh);
        ldm4(smem_u32(sBl + (wn + lr)*PAD + ks*16 + lc), bl);
#pragma unroll
        for (int mt = 0; mt < 4; ++mt) {
            uint32_t a[4];
            ldm4(smem_u32(sAh + (wm + mt*16 + lr)*PAD + ks*16 + lc), a);
            mma_bf16(c[mt*2+0], a, bh[0], bh[2]);
            mma_bf16(c[mt*2+1], a, bh[1], bh[3]);
            mma_bf16(c[mt*2+0], a, bl[0], bl[2]);
            mma_bf16(c[mt*2+1], a, bl[1], bl[3]);
            ldm4(smem_u32(sAl + (wm + mt*16 + lr)*PAD + ks*16 + lc), a);
            mma_bf16(c[mt*2+0], a, bh[0], bh[2]);
            mma_bf16(c[mt*2+1], a, bh[1], bh[3]);
        }
    }
}

__device__ __forceinline__ void store_split2(bf16* dh, bf16* dl, float a, float b) {
    bf16 h0 = __float2bfloat16(a), h1 = __float2bfloat16(b);
    bf162 hp; hp.x = h0; hp.y = h1; *(bf162*)dh = hp;
    bf16 l0 = __float2bfloat16(a - __bfloat162float(h0));
    bf16 l1 = __float2bfloat16(b - __bfloat162float(h1));
    bf162 lp; lp.x = l0; lp.y = l1; *(bf162*)dl = lp;
}

// ------------------------- kernel 1: splits + zero ---------------------------
__device__ __forceinline__ void split4(const float* s, bf16* dh, bf16* dl, int j) {
    float4 v = ((const float4*)s)[j];
    bf16 h0 = __float2bfloat16(v.x), h1 = __float2bfloat16(v.y);
    bf16 h2 = __float2bfloat16(v.z), h3 = __float2bfloat16(v.w);
    bf162 p;
    p.x = h0; p.y = h1; ((bf162*)dh)[j*2]   = p;
    p.x = h2; p.y = h3; ((bf162*)dh)[j*2+1] = p;
    bf16 l0 = __float2bfloat16(v.x - __bfloat162float(h0));
    bf16 l1 = __float2bfloat16(v.y - __bfloat162float(h1));
    bf16 l2 = __float2bfloat16(v.z - __bfloat162float(h2));
    bf16 l3 = __float2bfloat16(v.w - __bfloat162float(h3));
    p.x = l0; p.y = l1; ((bf162*)dl)[j*2]   = p;
    p.x = l2; p.y = l3; ((bf162*)dl)[j*2+1] = p;
}

__global__ __launch_bounds__(256) void split_all(
    const float* __restrict__ q, const float* __restrict__ k, const float* __restrict__ v,
    const float* __restrict__ wq, const float* __restrict__ wk, const float* __restrict__ wv,
    const float* __restrict__ wfc)
{
    const int NX4 = NX/4, NW4 = 512*512/4;
    int i = blockIdx.x*256 + threadIdx.x;
    if (i < 3*NX4) {
        int seg = i / NX4, j = i - seg*NX4;
        const float* s = (seg==0) ? q : (seg==1) ? k : v;
        bf16* dh = (seg==0) ? g_qxh : (seg==1) ? g_kxh : g_vxh;
        bf16* dl = (seg==0) ? g_qxl : (seg==1) ? g_kxl : g_vxl;
        split4(s, dh, dl, j);
    } else {
        int j = i - 3*NX4;
        if (j < 4*NW4) {
            int seg = j / NW4, jj = j - seg*NW4;
            const float* s = (seg==0) ? wq : (seg==1) ? wk : (seg==2) ? wv : wfc;
            split4(s, g_wh[seg], g_wl[seg], jj);
        } else {
            int j2 = j - 4*NW4;
            if (j2 < (HBC*SSEQ)/4) ((float4*)g_l)[j2] = make_float4(0.f,0.f,0.f,0.f);
        }
    }
}

// ------------------------- kernel 2: QKV projection (128x64 tiles) -----------
__global__ __launch_bounds__(256, 3) void proj_kernel(
    const float* __restrict__ bq, const float* __restrict__ bk, const float* __restrict__ bv)
{
    extern __shared__ __align__(16) bf16 smp[];
    const int t = threadIdx.x, lane = t & 31, wid = t >> 5;
    const int mat = blockIdx.y >> 3;
    const int n0  = (blockIdx.y & 7) * 64;
    const int m0  = blockIdx.x * 128;
    const bf16* Ah = (mat==0) ? g_qxh : (mat==1) ? g_kxh : g_vxh;
    const bf16* Al = (mat==0) ? g_qxl : (mat==1) ? g_kxl : g_vxl;
    const bf16* Bh = g_wh[mat];
    const bf16* Bl = g_wl[mat];
    const float* Bias = (mat==0) ? bq : (mat==1) ? bk : bv;

    float c[8][4] = {};
    const int wm = (wid >> 2) * 64, wn = (wid & 3) * 16;

    auto load = [&](int st, int k0) {
        bf16* s = smp + st*STG_S;
#pragma unroll
        for (int i = 0; i < 2; ++i) {
            int id = t + 256*i, r = id >> 2, cc = (id & 3) * 8;
            cp16(&s[r*PAD+cc],         &Ah[(size_t)(m0+r)*512 + k0+cc]);
            cp16(&s[ATILE + r*PAD+cc], &Al[(size_t)(m0+r)*512 + k0+cc]);
        }
        int r = t >> 2, cc = (t & 3) * 8;
        cp16(&s[2*ATILE + r*PAD+cc],         &Bh[(size_t)(n0+r)*512 + (t>>2, 0) + cc + 0]);
        cp16(&s[2*ATILE + r*PAD+cc],         &Bh[(size_t)(n0+r)*512 + k0 + cc]);
        cp16(&s[2*ATILE + BTILE + r*PAD+cc], &Bl[(size_t)(n0+r)*512 + k0 + cc]);
    };

    load(0, 0); cp_commit();
    for (int i = 0; i < 16; ++i) {
        cp_wait0();
        __syncthreads();
        if (i + 1 < 16) { load((i+1)&1, (i+1)*32); cp_commit(); }
        bf16* s = smp + (i&1)*STG_S;
        mma3_v2(s, s+ATILE, s+2*ATILE, s+2*ATILE+BTILE, lane, wm, wn, c);
    }

    const int g = lane >> 2, tg = lane & 3;
#pragma unroll
    for (int mt = 0; mt < 4; ++mt) {
        int r1 = m0 + wm + mt*16 + g;
        int r2 = r1 + 8;
#pragma unroll
        for (int nt = 0; nt < 2; ++nt) {
            float* cc = c[mt*2+nt];
            int f = n0 + wn + nt*8 + tg*2;
            float b0 = Bias[f], b1 = Bias[f+1];
            float v0 = cc[0]+b0, v1 = cc[1]+b1, v2 = cc[2]+b0, v3 = cc[3]+b1;
            if (mat == 0) { v0 *= 0.125f; v1 *= 0.125f; v2 *= 0.125f; v3 *= 0.125f; }
            int h = f >> 6, dk = f & 63;
            int bb1 = r1 >> 11, s1 = r1 & 2047;
            int bb2 = r2 >> 11, s2 = r2 & 2047;
            size_t o1 = (((size_t)(h*BBATCH+bb1))*SSEQ + s1)*DKH + dk;
            size_t o2 = (((size_t)(h*BBATCH+bb2))*SSEQ + s2)*DKH + dk;
            if (mat == 2) {
                *(float2*)&g_vf[o1] = make_float2(v0, v1);
                *(float2*)&g_vf[o2] = make_float2(v2, v3);
            } else if (mat == 0) {
                store_split2(g_Qh+o1, g_Ql+o1, v0, v1);
                store_split2(g_Qh+o2, g_Ql+o2, v2, v3);
            } else {
                store_split2(g_Kh+o1, g_Kl+o1, v0, v1);
                store_split2(g_Kh+o2, g_Kl+o2, v2, v3);
            }
        }
    }
}

// ------------------------- kernel 3: V transpose + split ---------------------
__global__ void vtrans_kernel() {
    __shared__ float tile[32][33];
    const int hb = blockIdx.z, s0 = blockIdx.x*32, d0 = blockIdx.y*32;
    const int x = threadIdx.x, y0 = threadIdx.y;
    for (int y = y0; y < 32; y += 8)
        tile[y][x] = g_vf[((size_t)hb*SSEQ + s0 + y)*DKH + d0 + x];
    __syncthreads();
    for (int y = y0; y < 32; y += 8) {
        float val = tile[x][y];
        bf16 h = __float2bfloat16(val);
        bf16 l = __float2bfloat16(val - __bfloat162float(h));
        size_t o = ((size_t)hb*DKH + d0 + y)*SSEQ + s0 + x;
        g_Vth[o] = h; g_Vtl[o] = l;
    }
}

// ------------------------- kernel 4: E = exp(QK^T/8) + row sums (128x64) -----
__global__ __launch_bounds__(256, 3) void e_kernel(float* __restrict__ attn) {
    extern __shared__ __align__(16) bf16 smp[];
    const int t = threadIdx.x, lane = t & 31, wid = t >> 5;
    const int hb = blockIdx.z;
    const int m0 = blockIdx.x * 128, n0 = blockIdx.y * 64;
    float c[8][4] = {};
    const int wm = (wid >> 2) * 64, wn = (wid & 3) * 16;

    auto load = [&](int st, int k0) {
        bf16* s = smp + st*STG_S;
#pragma unroll
        for (int i = 0; i < 2; ++i) {
            int id = t + 256*i, r = id >> 2, cc = (id & 3) * 8;
            cp16(&s[r*PAD+cc],         &g_Qh[((size_t)hb*SSEQ + m0+r)*DKH + k0+cc]);
            cp16(&s[ATILE + r*PAD+cc], &g_Ql[((size_t)hb*SSEQ + m0+r)*DKH + k0+cc]);
        }
        int r = t >> 2, cc = (t & 3) * 8;
        cp16(&s[2*ATILE + r*PAD+cc],         &g_Kh[((size_t)hb*SSEQ + n0+r)*DKH + k0+cc]);
        cp16(&s[2*ATILE + BTILE + r*PAD+cc], &g_Kl[((size_t)hb*SSEQ + n0+r)*DKH + k0+cc]);
    };

    load(0, 0); cp_commit();
    for (int i = 0; i < 2; ++i) {
        cp_wait0();
        __syncthreads();
        if (i + 1 < 2) { load((i+1)&1, 32); cp_commit(); }
        bf16* s = smp + (i&1)*STG_S;
        mma3_v2(s, s+ATILE, s+2*ATILE, s+2*ATILE+BTILE, lane, wm, wn, c);
    }

    const int g = lane >> 2, tg = lane & 3;
#pragma unroll
    for (int mt = 0; mt < 4; ++mt) {
        int r1 = m0 + wm + mt*16 + g;
        int r2 = r1 + 8;
        float s1 = 0.f, s2 = 0.f;
#pragma unroll
        for (int nt = 0; nt < 2; ++nt) {
            float* cc = c[mt*2+nt];
            int col = n0 + wn + nt*8 + tg*2;
            float e0 = __expf(cc[0]), e1 = __expf(cc[1]);
            float e2 = __expf(cc[2]), e3 = __expf(cc[3]);
            *(float2*)&attn[((size_t)hb*SSEQ + r1)*SSEQ + col] = make_float2(e0, e1);
            *(float2*)&attn[((size_t)hb*SSEQ + r2)*SSEQ + col] = make_float2(e2, e3);
            s1 += e0 + e1; s2 += e2 + e3;
        }
        s1 += __shfl_xor_sync(0xffffffffu, s1, 1);
        s1 += __shfl_xor_sync(0xffffffffu, s1, 2);
        s2 += __shfl_xor_sync(0xffffffffu, s2, 1);
        s2 += __shfl_xor_sync(0xffffffffu, s2, 2);
        if (tg == 0) {
            atomicAdd(&g_l[hb*SSEQ + r1], s1);
            atomicAdd(&g_l[hb*SSEQ + r2], s2);
        }
    }
}

// ------------------------- kernel 5: normalize + O = P V ---------------------
__global__ __launch_bounds__(256) void pv_kernel(float* __restrict__ attn) {
    extern __shared__ __align__(16) bf16 smp[];
    float* sInv = (float*)(smp + 2*STG_PV);
    const int t = threadIdx.x, lane = t & 31, wid = t >> 5;
    const int hb = blockIdx.y;
    const int m0 = blockIdx.x * 128;
    if (t < 128) sInv[t] = 1.0f / g_l[hb*SSEQ + m0 + t];
    __syncthreads();

    float c[8][4] = {};
    const int wm = (wid >> 2) * 64, wn = (wid & 3) * 16;

    auto ldP = [&](int k0, float4* pe) {
#pragma unroll
        for (int i = 0; i < 4; ++i) {
            int id = t + 256*i, r = id >> 3, cc = (id & 7) * 4;
            pe[i] = *(const float4*)&attn[((size_t)hb*SSEQ + m0 + r)*SSEQ + k0 + cc];
        }
    };
    auto stP = [&](int st, int k0, const float4* pe) {
        bf16* Ph = smp + st*STG_PV;
        bf16* Pl = Ph + ATILE;
#pragma unroll
        for (int i = 0; i < 4; ++i) {
            int id = t + 256*i, r = id >> 3, cc = (id & 7) * 4;
            float inv = sInv[r];
            float4 e4 = pe[i];
            e4.x *= inv; e4.y *= inv; e4.z *= inv; e4.w *= inv;
            *(float4*)&attn[((size_t)hb*SSEQ + m0 + r)*SSEQ + k0 + cc] = e4;
            bf16 h0 = __float2bfloat16(e4.x), h1 = __float2bfloat16(e4.y);
            bf16 h2 = __float2bfloat16(e4.z), h3 = __float2bfloat16(e4.w);
            bf162 p;
            p.x = h0; p.y = h1; ((bf162*)&Ph[r*PAD+cc])[0] = p;
            p.x = h2; p.y = h3; ((bf162*)&Ph[r*PAD+cc])[1] = p;
            bf16 l0 = __float2bfloat16(e4.x - __bfloat162float(h0));
            bf16 l1 = __float2bfloat16(e4.y - __bfloat162float(h1));
            bf16 l2 = __float2bfloat16(e4.z - __bfloat162float(h2));
            bf16 l3 = __float2bfloat16(e4.w - __bfloat162float(h3));
            p.x = l0; p.y = l1; ((bf162*)&Pl[r*PAD+cc])[0] = p;
            p.x = l2; p.y = l3; ((bf162*)&Pl[r*PAD+cc])[1] = p;
        }
    };
    auto ldV = [&](int st, int k0) {
        bf16* Vh = smp + st*STG_PV + 2*ATILE;
        bf16* Vl = Vh + BTILE;
        int r = t >> 2, cc = (t & 3) * 8;
        cp16(&Vh[r*PAD+cc], &g_Vth[((size_t)hb*DKH + r)*SSEQ + k0+cc]);
        cp16(&Vl[r*PAD+cc], &g_Vtl[((size_t)hb*DKH + r)*SSEQ + k0+cc]);
    };

    float4 pe[4];
    ldP(0, pe);
    ldV(0, 0); cp_commit();
    stP(0, 0, pe);

    for (int i = 0; i < 64; ++i) {
        cp_wait0();
        __syncthreads();
        if (i + 1 < 64) {
            ldP((i+1)*32, pe);
            ldV((i+1)&1, (i+1)*32); cp_commit();
        }
        bf16* s = smp + (i&1)*STG_PV;
        mma3_v2(s, s+ATILE, s+2*ATILE, s+2*ATILE+BTILE, lane, wm, wn, c);
        if (i + 1 < 64) stP((i+1)&1, (i+1)*32, pe);
    }

    const int g = lane >> 2, tg = lane & 3;
    const int b = hb & 3, h = hb >> 2;
#pragma unroll
    for (int mt = 0; mt < 4; ++mt) {
        int r1 = m0 + wm + mt*16 + g;
        int r2 = r1 + 8;
#pragma unroll
        for (int nt = 0; nt < 2; ++nt) {
            float* cc = c[mt*2+nt];
            int col = wn + nt*8 + tg*2;
            size_t o1 = ((size_t)(b*SSEQ + r1))*DMOD + h*DKH + col;
            size_t o2 = ((size_t)(b*SSEQ + r2))*DMOD + h*DKH + col;
            store_split2(g_ch+o1, g_cl+o1, cc[0], cc[1]);
            store_split2(g_ch+o2, g_cl+o2, cc[2], cc[3]);
        }
    }
}

// ------------------------- kernel 6: FC + bias + residual (128x64) -----------
__global__ __launch_bounds__(256, 3) void fc_kernel(
    const float* __restrict__ bfc, const float* __restrict__ resid)
{
    extern __shared__ __align__(16) bf16 smp[];
    const int t = threadIdx.x, lane = t & 31, wid = t >> 5;
    const int n0 = blockIdx.y * 64;
    const int m0 = blockIdx.x * 128;
    float c[8][4] = {};
    const int wm = (wid >> 2) * 64, wn = (wid & 3) * 16;

    auto load = [&](int st, int k0) {
        bf16* s = smp + st*STG_S;
#pragma unroll
        for (int i = 0; i < 2; ++i) {
            int id = t + 256*i, r = id >> 2, cc = (id & 3) * 8;
            cp16(&s[r*PAD+cc],         &g_ch[(size_t)(m0+r)*512 + k0+cc]);
            cp16(&s[ATILE + r*PAD+cc], &g_cl[(size_t)(m0+r)*512 + k0+cc]);
        }
        int r = t >> 2, cc = (t & 3) * 8;
        cp16(&s[2*ATILE + r*PAD+cc],         &g_wh[3][(size_t)(n0+r)*512 + k0+cc]);
        cp16(&s[2*ATILE + BTILE + r*PAD+cc], &g_wl[3][(size_t)(n0+r)*512 + k0+cc]);
    };

    load(0, 0); cp_commit();
    for (int i = 0; i < 16; ++i) {
        cp_wait0();
        __syncthreads();
        if (i + 1 < 16) { load((i+1)&1, (i+1)*32); cp_commit(); }
        bf16* s = smp + (i&1)*STG_S;
        mma3_v2(s, s+ATILE, s+2*ATILE, s+2*ATILE+BTILE, lane, wm, wn, c);
    }

    const int g = lane >> 2, tg = lane & 3;
#pragma unroll
    for (int mt = 0; mt < 4; ++mt) {
        int r1 = m0 + wm + mt*16 + g;
        int r2 = r1 + 8;
#pragma unroll
        for (int nt = 0; nt < 2; ++nt) {
            float* cc = c[mt*2+nt];
            int d = n0 + wn + nt*8 + tg*2;
            float b0 = bfc[d], b1 = bfc[d+1];
            float v0 = cc[0] + b0 + resid[(size_t)r1*512 + d];
            float v1 = cc[1] + b1 + resid[(size_t)r1*512 + d + 1];
            float v2 = cc[2] + b0 + resid[(size_t)r2*512 + d];
            float v3 = cc[3] + b1 + resid[(size_t)r2*512 + d + 1];
            *(float2*)&g_x[(size_t)r1*512 + d] = make_float2(v0, v1);
            *(float2*)&g_x[(size_t)r2*512 + d] = make_float2(v2, v3);
        }
    }
}

// ------------------------- kernel 7: LayerNorm -------------------------------
__global__ __launch_bounds__(256) void ln_kernel(
    const float* __restrict__ gam, const float* __restrict__ bet,
    float* __restrict__ out)
{
    const int row = blockIdx.x, t = threadIdx.x;
    const float* xr = &g_x[(size_t)row * DMOD];
    float x1 = xr[t], x2 = xr[t + 256];
    float s  = x1 + x2;
    float sq = x1*x1 + x2*x2;
#pragma unroll
    for (int o = 16; o; o >>= 1) {
        s  += __shfl_xor_sync(0xffffffffu, s,  o);
        sq += __shfl_xor_sync(0xffffffffu, sq, o);
    }
    __shared__ float ws[8], wq[8];
    if ((t & 31) == 0) { ws[t >> 5] = s; wq[t >> 5] = sq; }
    __syncthreads();
    float S1 = 0.f, S2 = 0.f;
#pragma unroll
    for (int i = 0; i < 8; ++i) { S1 += ws[i]; S2 += wq[i]; }
    const float mu  = S1 * (1.0f / 512.0f);
    const float var = S2 * (1.0f / 512.0f) - mu * mu;
    const float rs  = rsqrtf(var + 1e-5f);
    out[(size_t)row*DMOD + t]       = (x1 - mu) * rs * gam[t]       + bet[t];
    out[(size_t)row*DMOD + t + 256] = (x2 - mu) * rs * gam[t + 256] + bet[t + 256];
}

// ------------------------- launch --------------------------------------------
extern "C" void kernel_launch(void* const* d_in, const int* in_sizes, int n_in,
                              void* d_out, int out_size) {
    const float* q   = (const float*)d_in[0];
    const float* k   = (const float*)d_in[1];
    const float* v   = (const float*)d_in[2];
    const float* wqs = (const float*)d_in[3];
    const float* bqs = (const float*)d_in[4];
    const float* wks = (const float*)d_in[5];
    const float* bks = (const float*)d_in[6];
    const float* wvs = (const float*)d_in[7];
    const float* bvs = (const float*)d_in[8];
    const float* wfc = (const float*)d_in[9];
    const float* bfc = (const float*)d_in[10];
    const float* lng = (const float*)d_in[11];
    const float* lnb = (const float*)d_in[12];

    float* out      = (float*)d_out;
    float* out_attn = out + (size_t)BBATCH * SSEQ * DMOD;

    cudaFuncSetAttribute(proj_kernel, cudaFuncAttributeMaxDynamicSharedMemorySize, SMEM_S);
    cudaFuncSetAttribute(e_kernel,    cudaFuncAttributeMaxDynamicSharedMemorySize, SMEM_S);
    cudaFuncSetAttribute(pv_kernel,   cudaFuncAttributeMaxDynamicSharedMemorySize, SMEM_PV);
    cudaFuncSetAttribute(fc_kernel,   cudaFuncAttributeMaxDynamicSharedMemorySize, SMEM_S);

    const int nsplit = 3*(NX/4) + 4*(512*512/4) + (HBC*SSEQ)/4;
    split_all<<<(nsplit + 255)/256, 256>>>(q, k, v, wqs, wks, wvs, wfc);
    proj_kernel<<<dim3(64, 24), 256, SMEM_S>>>(bqs, bks, bvs);
    vtrans_kernel<<<dim3(64, 2, 32), dim3(32, 8)>>>();
    e_kernel<<<dim3(16, 32, 32), 256, SMEM_S>>>(out_attn);
    pv_kernel<<<dim3(16, 32), 256, SMEM_PV>>>(out_attn);
    fc_kernel<<<dim3(64, 8), 256, SMEM_S>>>(bfc, q);
    ln_kernel<<<BBATCH * SSEQ, 256>>>(lng, lnb, out);
}